// round 5
// baseline (speedup 1.0000x reference)
#include <cuda_runtime.h>
#include <cuda_bf16.h>
#include <cstdint>

#define N_NODES 50000
#define N_EDGES 600000
#define F 128
#define NB_SCAN 196   // ceil(50000/256)

// ---------------- scratch (static device globals; no runtime allocation) ----
__device__ float g_h1[N_NODES * F];
__device__ float g_h2[N_NODES * F];
__device__ int   g_rowptr[N_NODES + 1];
__device__ int   g_cursor[N_NODES];
__device__ float g_invdeg[N_NODES];
__device__ int   g_csrsrc[N_EDGES];
__device__ int   g_bsum[NB_SCAN];
__device__ int   g_boff[NB_SCAN];

// ---------------- CSR build -------------------------------------------------
__global__ void zero_counts_kernel() {
    int i = blockIdx.x * blockDim.x + threadIdx.x;
    if (i < N_NODES) g_cursor[i] = 0;
}

__global__ void count_kernel(const int* __restrict__ dst) {
    int e = blockIdx.x * blockDim.x + threadIdx.x;
    if (e < N_EDGES) atomicAdd(&g_cursor[dst[e]], 1);
}

// Parallel scan over counts: A (block-local scan) -> B (scan block sums) -> C (apply)
__global__ void scanA_kernel() {
    int i = blockIdx.x * 256 + threadIdx.x;
    int c = (i < N_NODES) ? g_cursor[i] : 0;
    __shared__ int s[256];
    s[threadIdx.x] = c;
    __syncthreads();
#pragma unroll
    for (int off = 1; off < 256; off <<= 1) {
        int v = (threadIdx.x >= off) ? s[threadIdx.x - off] : 0;
        __syncthreads();
        s[threadIdx.x] += v;
        __syncthreads();
    }
    int incl = s[threadIdx.x];
    if (i < N_NODES) {
        g_rowptr[i] = incl - c;                       // block-local exclusive
        g_invdeg[i] = 1.0f / (float)(c > 1 ? c : 1);
    }
    if (threadIdx.x == 255) g_bsum[blockIdx.x] = incl;
}

__global__ void scanB_kernel() {
    int b = threadIdx.x;
    int v = (b < NB_SCAN) ? g_bsum[b] : 0;
    __shared__ int s[256];
    s[b] = v;
    __syncthreads();
#pragma unroll
    for (int off = 1; off < 256; off <<= 1) {
        int w = (b >= off) ? s[b - off] : 0;
        __syncthreads();
        s[b] += w;
        __syncthreads();
    }
    if (b < NB_SCAN) g_boff[b] = s[b] - v;            // exclusive
    if (b == 0) g_rowptr[N_NODES] = s[NB_SCAN - 1];   // total = N_EDGES
}

__global__ void scanC_kernel() {
    int i = blockIdx.x * 256 + threadIdx.x;
    if (i < N_NODES) {
        int r = g_rowptr[i] + g_boff[blockIdx.x];
        g_rowptr[i] = r;
        g_cursor[i] = r;
    }
}

__global__ void fill_kernel(const int* __restrict__ src, const int* __restrict__ dst) {
    int e = blockIdx.x * blockDim.x + threadIdx.x;
    if (e < N_EDGES) {
        int d = dst[e];
        int pos = atomicAdd(&g_cursor[d], 1);
        g_csrsrc[pos] = src[e];
    }
}

// ---------------- tf32 helpers ----------------------------------------------
__device__ __forceinline__ uint32_t f2tf(float x) {
    uint32_t r;
    asm("cvt.rna.tf32.f32 %0, %1;" : "=r"(r) : "f"(x));
    return r;
}

__device__ __forceinline__ void mma_tf32(float* c, const uint32_t* a, const uint32_t* b) {
    asm volatile(
        "mma.sync.aligned.m16n8k8.row.col.f32.tf32.tf32.f32 "
        "{%0,%1,%2,%3}, {%4,%5,%6,%7}, {%8,%9}, {%0,%1,%2,%3};"
        : "+f"(c[0]), "+f"(c[1]), "+f"(c[2]), "+f"(c[3])
        : "r"(a[0]), "r"(a[1]), "r"(a[2]), "r"(a[3]),
          "r"(b[0]), "r"(b[1]));
}

#define PADA 36
#define PADB 136

// ---------------- fused SAGE layer: out = X@Ws + mean(X)@Wn + b -------------
// Phase 0: self term, A tiles streamed from X.
// Phase 1: neighbor term, A tiles = per-chunk CSR gather-mean built in smem.
// Block tile 128x128, BK=32, 8 warps (2m x 4n), m16n8k8 tf32.
__global__ __launch_bounds__(256, 2) void sage_layer_fused(
    const float* __restrict__ X,
    const float* __restrict__ Ws, const float* __restrict__ Wn,
    const float* __restrict__ bias,
    float* __restrict__ out, int do_relu)
{
    __shared__ uint32_t As[128 * PADA];
    __shared__ uint32_t Bs[32 * PADB];

    const int tid  = threadIdx.x;
    const int lane = tid & 31;
    const int wid  = tid >> 5;
    const int wm   = wid & 1;
    const int wn   = wid >> 1;
    const int g    = lane >> 2;
    const int tig  = lane & 3;
    const int bm   = blockIdx.x * 128;

    float c[4][4][4];
#pragma unroll
    for (int mi = 0; mi < 4; mi++)
#pragma unroll
        for (int ni = 0; ni < 4; ni++)
#pragma unroll
            for (int r = 0; r < 4; r++) c[mi][ni][r] = 0.f;

    for (int phase = 0; phase < 2; ++phase) {
        const float* W = phase ? Wn : Ws;

        for (int kc = 0; kc < 4; ++kc) {
            const int k0 = kc * 32;

            // ---- B tile (32k x 128n) from W, tf32-rounded (all threads)
#pragma unroll
            for (int i = 0; i < 4; i++) {
                int slot = tid + 256 * i;
                int kr = slot >> 5;
                int nb = (slot & 31) * 4;
                float4 v = *(const float4*)&W[(size_t)(k0 + kr) * F + nb];
                uint32_t* p = &Bs[kr * PADB + nb];
                p[0] = f2tf(v.x); p[1] = f2tf(v.y);
                p[2] = f2tf(v.z); p[3] = f2tf(v.w);
            }

            if (phase == 0) {
                // ---- A tile from X rows (coalesced float4)
#pragma unroll
                for (int i = 0; i < 4; i++) {
                    int slot = tid + 256 * i;
                    int r  = slot >> 3;
                    int kq = slot & 7;
                    int grow = bm + r;
                    float4 v = make_float4(0.f, 0.f, 0.f, 0.f);
                    if (grow < N_NODES)
                        v = *(const float4*)&X[(size_t)grow * F + k0 + kq * 4];
                    uint32_t* p = &As[r * PADA + kq * 4];
                    p[0] = f2tf(v.x); p[1] = f2tf(v.y);
                    p[2] = f2tf(v.z); p[3] = f2tf(v.w);
                }
            } else {
                // ---- A tile = neighbor-mean chunk via CSR gather.
                // Warp w handles rows [w*16, w*16+16); lane = k-column.
                for (int rr = 0; rr < 16; rr++) {
                    int r = wid * 16 + rr;
                    int node = bm + r;
                    float acc = 0.f;
                    if (node < N_NODES) {
                        int beg = __ldg(&g_rowptr[node]);
                        int end = __ldg(&g_rowptr[node + 1]);
                        if (beg < end) {
                            int s = __ldg(&g_csrsrc[beg]);   // prefetch (breaks 2-deep chain)
                            for (int i = beg; i < end; i++) {
                                int snext = (i + 1 < end) ? __ldg(&g_csrsrc[i + 1]) : 0;
                                acc += __ldg(&X[(size_t)s * F + k0 + lane]);
                                s = snext;
                            }
                            acc *= __ldg(&g_invdeg[node]);
                        }
                    }
                    As[r * PADA + lane] = f2tf(acc);
                }
            }
            __syncthreads();

#pragma unroll
            for (int ks = 0; ks < 4; ++ks) {
                uint32_t a[4][4];
                uint32_t b[4][2];
#pragma unroll
                for (int mi = 0; mi < 4; mi++) {
                    int r0 = wm * 64 + mi * 16 + g;
                    a[mi][0] = As[r0 * PADA + ks * 8 + tig];
                    a[mi][1] = As[(r0 + 8) * PADA + ks * 8 + tig];
                    a[mi][2] = As[r0 * PADA + ks * 8 + tig + 4];
                    a[mi][3] = As[(r0 + 8) * PADA + ks * 8 + tig + 4];
                }
#pragma unroll
                for (int ni = 0; ni < 4; ni++) {
                    int cb = wn * 32 + ni * 8 + g;
                    b[ni][0] = Bs[(ks * 8 + tig) * PADB + cb];
                    b[ni][1] = Bs[(ks * 8 + tig + 4) * PADB + cb];
                }
#pragma unroll
                for (int mi = 0; mi < 4; mi++)
#pragma unroll
                    for (int ni = 0; ni < 4; ni++)
                        mma_tf32(c[mi][ni], a[mi], b[ni]);
            }
            __syncthreads();
        }
    }

    // ---- epilogue: bias (+relu), float2 stores
#pragma unroll
    for (int mi = 0; mi < 4; mi++) {
        int row0 = bm + wm * 64 + mi * 16 + g;
#pragma unroll
        for (int ni = 0; ni < 4; ni++) {
            int col = wn * 32 + ni * 8 + tig * 2;
            float2 bb = *(const float2*)&bias[col];
            float2 o0, o1;
            o0.x = c[mi][ni][0] + bb.x;
            o0.y = c[mi][ni][1] + bb.y;
            o1.x = c[mi][ni][2] + bb.x;
            o1.y = c[mi][ni][3] + bb.y;
            if (do_relu) {
                o0.x = fmaxf(o0.x, 0.f); o0.y = fmaxf(o0.y, 0.f);
                o1.x = fmaxf(o1.x, 0.f); o1.y = fmaxf(o1.y, 0.f);
            }
            if (row0 < N_NODES)
                *(float2*)&out[(size_t)row0 * F + col] = o0;
            if (row0 + 8 < N_NODES)
                *(float2*)&out[(size_t)(row0 + 8) * F + col] = o1;
        }
    }
}

// ---------------- launch ----------------------------------------------------
extern "C" void kernel_launch(void* const* d_in, const int* in_sizes, int n_in,
                              void* d_out, int out_size)
{
    const float* feat = (const float*)d_in[0];
    const int*   src  = (const int*)d_in[1];
    const int*   dst  = (const int*)d_in[2];
    const float* W1s = (const float*)d_in[3];
    const float* W1n = (const float*)d_in[4];
    const float* b1  = (const float*)d_in[5];
    const float* W2s = (const float*)d_in[6];
    const float* W2n = (const float*)d_in[7];
    const float* b2  = (const float*)d_in[8];
    const float* W3s = (const float*)d_in[9];
    const float* W3n = (const float*)d_in[10];
    const float* b3  = (const float*)d_in[11];
    float* out = (float*)d_out;

    void* p;
    cudaGetSymbolAddress(&p, g_h1);   float* h1 = (float*)p;
    cudaGetSymbolAddress(&p, g_h2);   float* h2 = (float*)p;

    const int TB = 256;
    // CSR build
    zero_counts_kernel<<<(N_NODES + TB - 1) / TB, TB>>>();
    count_kernel<<<(N_EDGES + TB - 1) / TB, TB>>>(dst);
    scanA_kernel<<<NB_SCAN, 256>>>();
    scanB_kernel<<<1, 256>>>();
    scanC_kernel<<<NB_SCAN, 256>>>();
    fill_kernel<<<(N_EDGES + TB - 1) / TB, TB>>>(src, dst);

    const int gemm_grid = (N_NODES + 127) / 128;  // 391

    sage_layer_fused<<<gemm_grid, TB>>>(feat, W1s, W1n, b1, h1, 1);
    sage_layer_fused<<<gemm_grid, TB>>>(h1,   W2s, W2n, b2, h2, 1);
    sage_layer_fused<<<gemm_grid, TB>>>(h2,   W3s, W3n, b3, out, 0);
}

// round 6
// speedup vs baseline: 3.3760x; 3.3760x over previous
#include <cuda_runtime.h>
#include <cuda_bf16.h>
#include <cstdint>

#define N_NODES 50000
#define N_EDGES 600000
#define F 128
#define NB_SCAN 196   // ceil(50000/256)

// ---------------- scratch (static device globals; no runtime allocation) ----
__device__ float g_mean[N_NODES * F];
__device__ float g_h1[N_NODES * F];
__device__ float g_h2[N_NODES * F];
__device__ int   g_rowptr[N_NODES + 1];
__device__ int   g_cursor[N_NODES];
__device__ float g_invdeg[N_NODES];
__device__ int   g_csrsrc[N_EDGES];
__device__ int   g_bsum[NB_SCAN];
__device__ int   g_boff[NB_SCAN];

// ---------------- CSR build -------------------------------------------------
__global__ void zero_counts_kernel() {
    int i = blockIdx.x * blockDim.x + threadIdx.x;
    if (i < N_NODES) g_cursor[i] = 0;
}

__global__ void count_kernel(const int* __restrict__ dst) {
    int e = blockIdx.x * blockDim.x + threadIdx.x;
    if (e < N_EDGES) atomicAdd(&g_cursor[dst[e]], 1);
}

// Parallel scan: A (block-local scan) -> B (scan block sums) -> C (apply)
__global__ void scanA_kernel() {
    int i = blockIdx.x * 256 + threadIdx.x;
    int c = (i < N_NODES) ? g_cursor[i] : 0;
    __shared__ int s[256];
    s[threadIdx.x] = c;
    __syncthreads();
#pragma unroll
    for (int off = 1; off < 256; off <<= 1) {
        int v = (threadIdx.x >= off) ? s[threadIdx.x - off] : 0;
        __syncthreads();
        s[threadIdx.x] += v;
        __syncthreads();
    }
    int incl = s[threadIdx.x];
    if (i < N_NODES) {
        g_rowptr[i] = incl - c;                       // block-local exclusive
        g_invdeg[i] = 1.0f / (float)(c > 1 ? c : 1);
    }
    if (threadIdx.x == 255) g_bsum[blockIdx.x] = incl;
}

__global__ void scanB_kernel() {
    int b = threadIdx.x;
    int v = (b < NB_SCAN) ? g_bsum[b] : 0;
    __shared__ int s[256];
    s[b] = v;
    __syncthreads();
#pragma unroll
    for (int off = 1; off < 256; off <<= 1) {
        int w = (b >= off) ? s[b - off] : 0;
        __syncthreads();
        s[b] += w;
        __syncthreads();
    }
    if (b < NB_SCAN) g_boff[b] = s[b] - v;            // exclusive
    if (b == 0) g_rowptr[N_NODES] = s[NB_SCAN - 1];   // total = N_EDGES
}

__global__ void scanC_kernel() {
    int i = blockIdx.x * 256 + threadIdx.x;
    if (i < N_NODES) {
        int r = g_rowptr[i] + g_boff[blockIdx.x];
        g_rowptr[i] = r;
        g_cursor[i] = r;
    }
}

__global__ void fill_kernel(const int* __restrict__ src, const int* __restrict__ dst) {
    int e = blockIdx.x * blockDim.x + threadIdx.x;
    if (e < N_EDGES) {
        int d = dst[e];
        int pos = atomicAdd(&g_cursor[d], 1);
        g_csrsrc[pos] = src[e];
    }
}

// ---------------- neighbor mean aggregation (warp per node, no atomics) -----
// 50000 warps, float4 per lane: massive MLP, runs at the LTS/L2 cap.
__global__ void aggregate_kernel(const float* __restrict__ x) {
    int warp = (blockIdx.x * blockDim.x + threadIdx.x) >> 5;
    int lane = threadIdx.x & 31;
    if (warp >= N_NODES) return;

    int beg = g_rowptr[warp];
    int end = g_rowptr[warp + 1];

    float4 acc = make_float4(0.f, 0.f, 0.f, 0.f);
    for (int i = beg; i < end; i++) {
        int s = __ldg(&g_csrsrc[i]);
        float4 v = *(const float4*)&x[(size_t)s * F + lane * 4];
        acc.x += v.x; acc.y += v.y; acc.z += v.z; acc.w += v.w;
    }
    float inv = g_invdeg[warp];
    float4 o = make_float4(acc.x * inv, acc.y * inv, acc.z * inv, acc.w * inv);
    *(float4*)&g_mean[(size_t)warp * F + lane * 4] = o;
}

// ---------------- tf32 tensor-core fused SAGE GEMM --------------------------
__device__ __forceinline__ uint32_t f2tf(float x) {
    uint32_t r;
    asm("cvt.rna.tf32.f32 %0, %1;" : "=r"(r) : "f"(x));
    return r;
}

__device__ __forceinline__ void mma_tf32(float* c, const uint32_t* a, const uint32_t* b) {
    asm volatile(
        "mma.sync.aligned.m16n8k8.row.col.f32.tf32.tf32.f32 "
        "{%0,%1,%2,%3}, {%4,%5,%6,%7}, {%8,%9}, {%0,%1,%2,%3};"
        : "+f"(c[0]), "+f"(c[1]), "+f"(c[2]), "+f"(c[3])
        : "r"(a[0]), "r"(a[1]), "r"(a[2]), "r"(a[3]),
          "r"(b[0]), "r"(b[1]));
}

#define PADA 36
#define PADB 136

// out[M,128] = X @ Ws + mean @ Wn + b (optional relu)
// Block tile 128x128, BK=32, 8 warps (2m x 4n), m16n8k8 tf32.
// Global->register prefetch of the next k-chunk overlaps gmem latency with MMA.
__global__ __launch_bounds__(256, 2) void gemm_sage_tf32(
    const float* __restrict__ X,
    const float* __restrict__ MEAN,
    const float* __restrict__ Ws, const float* __restrict__ Wn,
    const float* __restrict__ bias,
    float* __restrict__ out, int do_relu)
{
    __shared__ uint32_t As[128 * PADA];  // 18432 B
    __shared__ uint32_t Bs[32 * PADB];   // 17408 B

    const int tid  = threadIdx.x;
    const int lane = tid & 31;
    const int wid  = tid >> 5;
    const int wm   = wid & 1;
    const int wn   = wid >> 1;
    const int g    = lane >> 2;
    const int tig  = lane & 3;
    const int bm   = blockIdx.x * 128;

    // fixed per-thread load mappings (4 slots each for A and B)
    // A: slot -> row = slot>>3, kq = slot&7
    // B: slot -> kr = slot>>5, nb = (slot&31)*4
    float c[4][4][4];
#pragma unroll
    for (int mi = 0; mi < 4; mi++)
#pragma unroll
        for (int ni = 0; ni < 4; ni++)
#pragma unroll
            for (int r = 0; r < 4; r++) c[mi][ni][r] = 0.f;

    for (int phase = 0; phase < 2; ++phase) {
        const float* A = phase ? MEAN : X;
        const float* W = phase ? Wn : Ws;

        float4 pa[4], pb[4];
        // preload chunk 0
#pragma unroll
        for (int i = 0; i < 4; i++) {
            int slot = tid + 256 * i;
            int r    = slot >> 3;
            int kq   = slot & 7;
            int grow = bm + r;
            pa[i] = make_float4(0.f, 0.f, 0.f, 0.f);
            if (grow < N_NODES)
                pa[i] = *(const float4*)&A[(size_t)grow * F + kq * 4];
            int kr = slot >> 5;
            int nb = (slot & 31) * 4;
            pb[i] = *(const float4*)&W[(size_t)kr * F + nb];
        }

        for (int kc = 0; kc < 4; ++kc) {
            // commit prefetched chunk to smem
#pragma unroll
            for (int i = 0; i < 4; i++) {
                int slot = tid + 256 * i;
                int r    = slot >> 3;
                int kq   = slot & 7;
                uint32_t* p = &As[r * PADA + kq * 4];
                p[0] = f2tf(pa[i].x); p[1] = f2tf(pa[i].y);
                p[2] = f2tf(pa[i].z); p[3] = f2tf(pa[i].w);
                int kr = slot >> 5;
                int nb = (slot & 31) * 4;
                uint32_t* q = &Bs[kr * PADB + nb];
                q[0] = f2tf(pb[i].x); q[1] = f2tf(pb[i].y);
                q[2] = f2tf(pb[i].z); q[3] = f2tf(pb[i].w);
            }
            __syncthreads();

            // prefetch next chunk (gmem latency hides under MMA below)
            if (kc < 3) {
                const int k0n = (kc + 1) * 32;
#pragma unroll
                for (int i = 0; i < 4; i++) {
                    int slot = tid + 256 * i;
                    int r    = slot >> 3;
                    int kq   = slot & 7;
                    int grow = bm + r;
                    pa[i] = make_float4(0.f, 0.f, 0.f, 0.f);
                    if (grow < N_NODES)
                        pa[i] = *(const float4*)&A[(size_t)grow * F + k0n + kq * 4];
                    int kr = slot >> 5;
                    int nb = (slot & 31) * 4;
                    pb[i] = *(const float4*)&W[(size_t)(k0n + kr) * F + nb];
                }
            }

#pragma unroll
            for (int ks = 0; ks < 4; ++ks) {
                uint32_t a[4][4];
                uint32_t b[4][2];
#pragma unroll
                for (int mi = 0; mi < 4; mi++) {
                    int r0 = wm * 64 + mi * 16 + g;
                    a[mi][0] = As[r0 * PADA + ks * 8 + tig];
                    a[mi][1] = As[(r0 + 8) * PADA + ks * 8 + tig];
                    a[mi][2] = As[r0 * PADA + ks * 8 + tig + 4];
                    a[mi][3] = As[(r0 + 8) * PADA + ks * 8 + tig + 4];
                }
#pragma unroll
                for (int ni = 0; ni < 4; ni++) {
                    int cb = wn * 32 + ni * 8 + g;
                    b[ni][0] = Bs[(ks * 8 + tig) * PADB + cb];
                    b[ni][1] = Bs[(ks * 8 + tig + 4) * PADB + cb];
                }
#pragma unroll
                for (int mi = 0; mi < 4; mi++)
#pragma unroll
                    for (int ni = 0; ni < 4; ni++)
                        mma_tf32(c[mi][ni], a[mi], b[ni]);
            }
            __syncthreads();
        }
    }

    // ---- epilogue: bias (+relu), float2 stores
#pragma unroll
    for (int mi = 0; mi < 4; mi++) {
        int row0 = bm + wm * 64 + mi * 16 + g;
#pragma unroll
        for (int ni = 0; ni < 4; ni++) {
            int col = wn * 32 + ni * 8 + tig * 2;
            float2 bb = *(const float2*)&bias[col];
            float2 o0, o1;
            o0.x = c[mi][ni][0] + bb.x;
            o0.y = c[mi][ni][1] + bb.y;
            o1.x = c[mi][ni][2] + bb.x;
            o1.y = c[mi][ni][3] + bb.y;
            if (do_relu) {
                o0.x = fmaxf(o0.x, 0.f); o0.y = fmaxf(o0.y, 0.f);
                o1.x = fmaxf(o1.x, 0.f); o1.y = fmaxf(o1.y, 0.f);
            }
            if (row0 < N_NODES)
                *(float2*)&out[(size_t)row0 * F + col] = o0;
            if (row0 + 8 < N_NODES)
                *(float2*)&out[(size_t)(row0 + 8) * F + col] = o1;
        }
    }
}

// ---------------- launch ----------------------------------------------------
extern "C" void kernel_launch(void* const* d_in, const int* in_sizes, int n_in,
                              void* d_out, int out_size)
{
    const float* feat = (const float*)d_in[0];
    const int*   src  = (const int*)d_in[1];
    const int*   dst  = (const int*)d_in[2];
    const float* W1s = (const float*)d_in[3];
    const float* W1n = (const float*)d_in[4];
    const float* b1  = (const float*)d_in[5];
    const float* W2s = (const float*)d_in[6];
    const float* W2n = (const float*)d_in[7];
    const float* b2  = (const float*)d_in[8];
    const float* W3s = (const float*)d_in[9];
    const float* W3n = (const float*)d_in[10];
    const float* b3  = (const float*)d_in[11];
    float* out = (float*)d_out;

    void* p;
    cudaGetSymbolAddress(&p, g_h1);   float* h1   = (float*)p;
    cudaGetSymbolAddress(&p, g_h2);   float* h2   = (float*)p;
    cudaGetSymbolAddress(&p, g_mean); float* mean = (float*)p;

    const int TB = 256;
    // CSR build (parallel scan)
    zero_counts_kernel<<<(N_NODES + TB - 1) / TB, TB>>>();
    count_kernel<<<(N_EDGES + TB - 1) / TB, TB>>>(dst);
    scanA_kernel<<<NB_SCAN, 256>>>();
    scanB_kernel<<<1, 256>>>();
    scanC_kernel<<<NB_SCAN, 256>>>();
    fill_kernel<<<(N_EDGES + TB - 1) / TB, TB>>>(src, dst);

    const int agg_grid  = (N_NODES + 7) / 8;      // 8 warps/block
    const int gemm_grid = (N_NODES + 127) / 128;  // 391

    // layer 1
    aggregate_kernel<<<agg_grid, TB>>>(feat);
    gemm_sage_tf32<<<gemm_grid, TB>>>(feat, mean, W1s, W1n, b1, h1, 1);
    // layer 2
    aggregate_kernel<<<agg_grid, TB>>>(h1);
    gemm_sage_tf32<<<gemm_grid, TB>>>(h1, mean, W2s, W2n, b2, h2, 1);
    // layer 3
    aggregate_kernel<<<agg_grid, TB>>>(h2);
    gemm_sage_tf32<<<gemm_grid, TB>>>(h2, mean, W3s, W3n, b3, out, 0);
}